// round 4
// baseline (speedup 1.0000x reference)
#include <cuda_runtime.h>
#include <cuda_bf16.h>

#define N_ITEMS 20000
#define ALPHA 0.2f
#define NEG_INF_V -9000000000000000.0f

__device__ float g_wa1[64];
__device__ float g_wa2[64];
__device__ float g_s1[N_ITEMS];   // precomputed item[n] . wa1

__global__ void precompute_wa(const float* __restrict__ W, const float* __restrict__ a) {
    int f = threadIdx.x;  // 0..63
    float s1 = 0.f, s2 = 0.f;
#pragma unroll
    for (int h = 0; h < 64; ++h) {
        float w = W[f * 64 + h];
        s1 += w * a[h];
        s2 += w * a[64 + h];
    }
    g_wa1[f] = s1;
    g_wa2[f] = s2;
}

// One warp per row n: s1[n] = item[n] . wa1
__global__ __launch_bounds__(256) void precompute_s1(const float* __restrict__ item) {
    const int warp = (blockIdx.x * blockDim.x + threadIdx.x) >> 5;
    const int lane = threadIdx.x & 31;
    if (warp >= N_ITEMS) return;
    float p = item[(size_t)warp * 64 + lane]      * g_wa1[lane]
            + item[(size_t)warp * 64 + 32 + lane] * g_wa1[32 + lane];
#pragma unroll
    for (int o = 16; o > 0; o >>= 1) p += __shfl_xor_sync(0xffffffffu, p, o);
    if (lane == 0) g_s1[warp] = p;
}

// One CTA per item row n. Entity tile register-resident (thread t holds
// f-range (t&15)*4..+3 of rows m = k*16 + (t>>4), k=0..3).
// Softmax replicated per warp, registers only, no max-subtraction
// (|e| bounded ~25 << 88; masked lanes underflow to exactly 0).
__global__ __launch_bounds__(256, 8) void gat_kernel(
    const float* __restrict__ item,
    const float* __restrict__ ent,
    const int*   __restrict__ adj,
    float*       __restrict__ out)
{
    __shared__ float dbuf[64];     // entity[m] . wa2
    __shared__ float part[8 * 64]; // per-warp output partials

    const int n    = blockIdx.x;
    const int t    = threadIdx.x;
    const int lane = t & 31;
    const int sub  = t & 15;       // f-chunk id
    const int grp  = t >> 4;       // 0..15 (m low bits)
    const int w    = t >> 5;       // warp id
    const float* eb = ent + (size_t)n * 4096;

    // Residual prefetch (held to the end by t<64)
    float itemres = 0.f;
    if (t < 64) itemres = item[(size_t)n * 64 + t];

    // adj prefetch (per-warp redundant; L1 hits after first warp)
    const int ja0 = adj[(size_t)n * 64 + lane];
    const int ja1 = adj[(size_t)n * 64 + 32 + lane];

    const float s1 = g_s1[n];  // uniform scalar
    const float4 w2 = *reinterpret_cast<const float4*>(&g_wa2[sub * 4]);

    // --- Entity tile loads (4x LDG.128 per thread, front-batched) ---
    float4 v[4];
#pragma unroll
    for (int k = 0; k < 4; ++k)
        v[k] = *reinterpret_cast<const float4*>(eb + k * 1024 + t * 4);

    // --- d[m] = entity[m].wa2 ---
    float d[4];
#pragma unroll
    for (int k = 0; k < 4; ++k)
        d[k] = v[k].x * w2.x + v[k].y * w2.y + v[k].z * w2.z + v[k].w * w2.w;
#pragma unroll
    for (int o = 1; o < 16; o <<= 1) {
#pragma unroll
        for (int k = 0; k < 4; ++k)
            d[k] += __shfl_xor_sync(0xffffffffu, d[k], o);
    }
    if (sub == 0) {
#pragma unroll
        for (int k = 0; k < 4; ++k)
            dbuf[k * 16 + grp] = d[k];
    }
    __syncthreads();

    // --- Softmax, replicated per warp, no max-subtraction ---
    float e0 = s1 + dbuf[lane];
    float e1 = s1 + dbuf[32 + lane];
    e0 = e0 > 0.f ? e0 : ALPHA * e0;
    e1 = e1 > 0.f ? e1 : ALPHA * e1;
    if (ja0 <= 0) e0 = NEG_INF_V;
    if (ja1 <= 0) e1 = NEG_INF_V;

    const float x0 = __expf(e0);   // masked -> exactly 0
    const float x1 = __expf(e1);
    float sm = x0 + x1;
#pragma unroll
    for (int o = 16; o > 0; o >>= 1) sm += __shfl_xor_sync(0xffffffffu, sm, o);
    const float inv  = 1.0f / sm;
    const float att0 = x0 * inv;   // lane holds att[m=lane]
    const float att1 = x1 * inv;   // lane holds att[m=lane+32]

    // Attention values this thread needs: m = k*16 + grp
    float am[4];
    am[0] = __shfl_sync(0xffffffffu, att0, grp & 15);
    am[1] = __shfl_sync(0xffffffffu, att0, 16 + (grp & 15));
    am[2] = __shfl_sync(0xffffffffu, att1, grp & 15);
    am[3] = __shfl_sync(0xffffffffu, att1, 16 + (grp & 15));

    // --- Weighted sum from registers ---
    float4 acc = make_float4(0.f, 0.f, 0.f, 0.f);
#pragma unroll
    for (int k = 0; k < 4; ++k) {
        acc.x = fmaf(am[k], v[k].x, acc.x);
        acc.y = fmaf(am[k], v[k].y, acc.y);
        acc.z = fmaf(am[k], v[k].z, acc.z);
        acc.w = fmaf(am[k], v[k].w, acc.w);
    }
    acc.x += __shfl_xor_sync(0xffffffffu, acc.x, 16);
    acc.y += __shfl_xor_sync(0xffffffffu, acc.y, 16);
    acc.z += __shfl_xor_sync(0xffffffffu, acc.z, 16);
    acc.w += __shfl_xor_sync(0xffffffffu, acc.w, 16);

    if (lane < 16)
        *reinterpret_cast<float4*>(&part[w * 64 + sub * 4]) = acc;
    __syncthreads();

    // --- Final: reduce 8 warp partials + residual, store ---
    if (t < 64) {
        float r = part[t]       + part[64 + t]  + part[128 + t] + part[192 + t]
                + part[256 + t] + part[320 + t] + part[384 + t] + part[448 + t]
                + itemres;
        out[(size_t)n * 64 + t] = r;
    }
}

extern "C" void kernel_launch(void* const* d_in, const int* in_sizes, int n_in,
                              void* d_out, int out_size) {
    const float* item = (const float*)d_in[0];
    const float* ent  = (const float*)d_in[1];
    const int*   adj  = (const int*)d_in[2];
    const float* W    = (const float*)d_in[3];
    const float* a    = (const float*)d_in[4];
    float* out = (float*)d_out;

    precompute_wa<<<1, 64>>>(W, a);
    precompute_s1<<<(N_ITEMS * 32 + 255) / 256, 256>>>(item);
    gat_kernel<<<N_ITEMS, 256>>>(item, ent, adj, out);
}

// round 5
// speedup vs baseline: 1.1409x; 1.1409x over previous
#include <cuda_runtime.h>
#include <cuda_bf16.h>

#define N_ITEMS 20000
#define ALPHA 0.2f
#define NEG_INF_V -9000000000000000.0f
#define GRID 608   // 4 CTAs/SM x 152 SMs (persistent)

// Load 16KB entity tile for row (n) into register file4 array (v).
#define LOADT(n, v)                                                          \
    {                                                                        \
        const float* _eb = ent + (size_t)(n) * 4096;                         \
        _Pragma("unroll")                                                    \
        for (int _k = 0; _k < 4; ++_k)                                       \
            v[_k] = *reinterpret_cast<const float4*>(_eb + _k * 1024 + t * 4);\
    }

// Full per-row processing using tile registers (v).
#define BODY(n, v)                                                           \
    {                                                                        \
        const size_t _b = (size_t)(n) * 64;                                  \
        const float _it0 = item[_b + lane];                                  \
        const float _it1 = item[_b + 32 + lane];                             \
        const int   _ja0 = adj[_b + lane];                                   \
        const int   _ja1 = adj[_b + 32 + lane];                              \
                                                                             \
        /* d-phase: 4 partial dots, transpose-reduce over 16 lanes (5 shfl) */\
        float _d0 = v[0].x * w2.x + v[0].y * w2.y + v[0].z * w2.z + v[0].w * w2.w; \
        float _d1 = v[1].x * w2.x + v[1].y * w2.y + v[1].z * w2.z + v[1].w * w2.w; \
        float _d2 = v[2].x * w2.x + v[2].y * w2.y + v[2].z * w2.z + v[2].w * w2.w; \
        float _d3 = v[3].x * w2.x + v[3].y * w2.y + v[3].z * w2.z + v[3].w * w2.w; \
        float _a01 = (sub & 1) ? _d1 : _d0;                                  \
        float _s01 = (sub & 1) ? _d0 : _d1;                                  \
        _a01 += __shfl_xor_sync(0xffffffffu, _s01, 1);                       \
        float _a23 = (sub & 1) ? _d3 : _d2;                                  \
        float _s23 = (sub & 1) ? _d2 : _d3;                                  \
        _a23 += __shfl_xor_sync(0xffffffffu, _s23, 1);                       \
        float _keep = (sub & 2) ? _a23 : _a01;                               \
        float _send = (sub & 2) ? _a01 : _a23;                               \
        float _s = _keep + __shfl_xor_sync(0xffffffffu, _send, 2);           \
        _s += __shfl_xor_sync(0xffffffffu, _s, 4);                           \
        _s += __shfl_xor_sync(0xffffffffu, _s, 8);                           \
        if (sub < 4) dbuf[sub * 16 + grp] = _s;  /* d_j at lane j=sub&3 */   \
        __syncthreads();                                                     \
                                                                             \
        /* s1 = item[n].wa1, replicated per warp (5 shfl) */                 \
        float _p = _it0 * wa1s[lane] + _it1 * wa1s[32 + lane];               \
        _Pragma("unroll")                                                    \
        for (int _o = 16; _o > 0; _o >>= 1)                                  \
            _p += __shfl_xor_sync(0xffffffffu, _p, _o);                      \
                                                                             \
        /* masked leaky-relu softmax, no max-subtraction (|e|<~30 << 88) */  \
        float _e0 = _p + dbuf[lane];                                         \
        float _e1 = _p + dbuf[32 + lane];                                    \
        _e0 = _e0 > 0.f ? _e0 : ALPHA * _e0;                                 \
        _e1 = _e1 > 0.f ? _e1 : ALPHA * _e1;                                 \
        if (_ja0 <= 0) _e0 = NEG_INF_V;                                      \
        if (_ja1 <= 0) _e1 = NEG_INF_V;                                      \
        const float _x0 = __expf(_e0);                                       \
        const float _x1 = __expf(_e1);                                       \
        float _sm = _x0 + _x1;                                               \
        _Pragma("unroll")                                                    \
        for (int _o = 16; _o > 0; _o >>= 1)                                  \
            _sm += __shfl_xor_sync(0xffffffffu, _sm, _o);                    \
        const float _inv = 1.0f / _sm;                                       \
        const float _att0 = _x0 * _inv;                                      \
        const float _att1 = _x1 * _inv;                                      \
        const float _am0 = __shfl_sync(0xffffffffu, _att0, grp);             \
        const float _am1 = __shfl_sync(0xffffffffu, _att0, 16 + grp);        \
        const float _am2 = __shfl_sync(0xffffffffu, _att1, grp);             \
        const float _am3 = __shfl_sync(0xffffffffu, _att1, 16 + grp);        \
                                                                             \
        /* weighted sum from registers */                                    \
        float4 _acc;                                                         \
        _acc.x = _am0 * v[0].x; _acc.y = _am0 * v[0].y;                      \
        _acc.z = _am0 * v[0].z; _acc.w = _am0 * v[0].w;                      \
        _acc.x = fmaf(_am1, v[1].x, _acc.x); _acc.y = fmaf(_am1, v[1].y, _acc.y); \
        _acc.z = fmaf(_am1, v[1].z, _acc.z); _acc.w = fmaf(_am1, v[1].w, _acc.w); \
        _acc.x = fmaf(_am2, v[2].x, _acc.x); _acc.y = fmaf(_am2, v[2].y, _acc.y); \
        _acc.z = fmaf(_am2, v[2].z, _acc.z); _acc.w = fmaf(_am2, v[2].w, _acc.w); \
        _acc.x = fmaf(_am3, v[3].x, _acc.x); _acc.y = fmaf(_am3, v[3].y, _acc.y); \
        _acc.z = fmaf(_am3, v[3].z, _acc.z); _acc.w = fmaf(_am3, v[3].w, _acc.w); \
        _acc.x += __shfl_xor_sync(0xffffffffu, _acc.x, 16);                  \
        _acc.y += __shfl_xor_sync(0xffffffffu, _acc.y, 16);                  \
        _acc.z += __shfl_xor_sync(0xffffffffu, _acc.z, 16);                  \
        _acc.w += __shfl_xor_sync(0xffffffffu, _acc.w, 16);                  \
        if (lane < 16)                                                       \
            *reinterpret_cast<float4*>(&part[w * 64 + sub * 4]) = _acc;      \
        __syncthreads();                                                     \
                                                                             \
        if (t < 64) {                                                        \
            float _r = part[t]       + part[64 + t]  + part[128 + t]         \
                     + part[192 + t] + part[256 + t] + part[320 + t]         \
                     + part[384 + t] + part[448 + t]                         \
                     + ((w == 0) ? _it0 : _it1);                             \
            out[_b + t] = _r;                                                \
        }                                                                    \
    }

__global__ __launch_bounds__(256, 4) void gat_kernel(
    const float* __restrict__ item,
    const float* __restrict__ ent,
    const int*   __restrict__ adj,
    const float* __restrict__ W,
    const float* __restrict__ a,
    float*       __restrict__ out)
{
    __shared__ float wa1s[64];
    __shared__ float wa2s[64];
    __shared__ float dbuf[64];
    __shared__ float part[8 * 64];

    const int t    = threadIdx.x;
    const int lane = t & 31;
    const int sub  = t & 15;
    const int grp  = t >> 4;
    const int w    = t >> 5;
    const int S    = gridDim.x;

    // --- Prologue: wa1 = W@a1, wa2 = W@a2 (once per CTA) ---
    {
        const int f = t >> 2, q = t & 3;
        const float* wr = W + f * 64 + q * 16;
        float p1 = 0.f, p2 = 0.f;
#pragma unroll
        for (int i = 0; i < 4; ++i) {
            float4 wv = *reinterpret_cast<const float4*>(wr + i * 4);
            float4 y1 = *reinterpret_cast<const float4*>(a + q * 16 + i * 4);
            float4 y2 = *reinterpret_cast<const float4*>(a + 64 + q * 16 + i * 4);
            p1 += wv.x * y1.x + wv.y * y1.y + wv.z * y1.z + wv.w * y1.w;
            p2 += wv.x * y2.x + wv.y * y2.y + wv.z * y2.z + wv.w * y2.w;
        }
        p1 += __shfl_xor_sync(0xffffffffu, p1, 1);
        p1 += __shfl_xor_sync(0xffffffffu, p1, 2);
        p2 += __shfl_xor_sync(0xffffffffu, p2, 1);
        p2 += __shfl_xor_sync(0xffffffffu, p2, 2);
        if (q == 0) { wa1s[f] = p1; wa2s[f] = p2; }
    }
    __syncthreads();
    const float4 w2 = *reinterpret_cast<const float4*>(&wa2s[sub * 4]);

    // --- Persistent grid-stride loop, double-buffered tile prefetch ---
    float4 vA[4], vB[4];
    int n = blockIdx.x;
    LOADT(n, vA);
    while (true) {
        const int nB = n + S;
        if (nB < N_ITEMS) LOADT(nB, vB);
        BODY(n, vA);
        if (nB >= N_ITEMS) break;
        n = nB + S;
        if (n < N_ITEMS) LOADT(n, vA);
        BODY(nB, vB);
        if (n >= N_ITEMS) break;
    }
}

extern "C" void kernel_launch(void* const* d_in, const int* in_sizes, int n_in,
                              void* d_out, int out_size) {
    const float* item = (const float*)d_in[0];
    const float* ent  = (const float*)d_in[1];
    const int*   adj  = (const int*)d_in[2];
    const float* W    = (const float*)d_in[3];
    const float* a    = (const float*)d_in[4];
    float* out = (float*)d_out;

    gat_kernel<<<GRID, 256>>>(item, ent, adj, W, a, out);
}

// round 6
// speedup vs baseline: 1.1763x; 1.0310x over previous
#include <cuda_runtime.h>
#include <cuda_bf16.h>

#define N_ITEMS 20000
#define ALPHA 0.2f
#define NEG_INF_V -9000000000000000.0f
#define GRID 608   // 4 CTAs/SM x 152 SMs (persistent)

// Issue per-lane adj loads for row n (64 ints -> 2 per lane).
#define LOADJ(n, j0, j1)                                                     \
    {                                                                        \
        const size_t _b = (size_t)(n) * 64;                                  \
        j0 = adj[_b + lane];                                                 \
        j1 = adj[_b + 32 + lane];                                            \
    }

// 4-bit mask for this thread's rows m = k*16+grp from per-lane adj regs.
#define MASKOF(j0, j1, mk)                                                   \
    {                                                                        \
        const int _f0 = __shfl_sync(0xffffffffu, j0, grp);                   \
        const int _f1 = __shfl_sync(0xffffffffu, j0, 16 + grp);              \
        const int _f2 = __shfl_sync(0xffffffffu, j1, grp);                   \
        const int _f3 = __shfl_sync(0xffffffffu, j1, 16 + grp);              \
        mk = (_f0 > 0 ? 1 : 0) | (_f1 > 0 ? 2 : 0)                           \
           | (_f2 > 0 ? 4 : 0) | (_f3 > 0 ? 8 : 0);                          \
    }

// Predicated tile load: only rows with adj=1 touch DRAM (~50% skipped).
#define LOADT_P(n, v, mk)                                                    \
    {                                                                        \
        const float* _eb = ent + (size_t)(n) * 4096;                         \
        _Pragma("unroll")                                                    \
        for (int _k = 0; _k < 4; ++_k) {                                     \
            if ((mk >> _k) & 1)                                              \
                v[_k] = *reinterpret_cast<const float4*>(_eb + _k * 1024 + t * 4); \
            else                                                             \
                v[_k] = make_float4(0.f, 0.f, 0.f, 0.f);                     \
        }                                                                    \
    }

// Full per-row processing using tile registers (v) and adj regs (j0,j1).
#define BODY(n, v, j0, j1)                                                   \
    {                                                                        \
        const size_t _b = (size_t)(n) * 64;                                  \
        const float _it0 = item[_b + lane];                                  \
        const float _it1 = item[_b + 32 + lane];                             \
                                                                             \
        /* d-phase: 4 partial dots, transpose-reduce over 16 lanes (5 shfl) */\
        float _d0 = v[0].x * w2.x + v[0].y * w2.y + v[0].z * w2.z + v[0].w * w2.w; \
        float _d1 = v[1].x * w2.x + v[1].y * w2.y + v[1].z * w2.z + v[1].w * w2.w; \
        float _d2 = v[2].x * w2.x + v[2].y * w2.y + v[2].z * w2.z + v[2].w * w2.w; \
        float _d3 = v[3].x * w2.x + v[3].y * w2.y + v[3].z * w2.z + v[3].w * w2.w; \
        float _a01 = (sub & 1) ? _d1 : _d0;                                  \
        float _s01 = (sub & 1) ? _d0 : _d1;                                  \
        _a01 += __shfl_xor_sync(0xffffffffu, _s01, 1);                       \
        float _a23 = (sub & 1) ? _d3 : _d2;                                  \
        float _s23 = (sub & 1) ? _d2 : _d3;                                  \
        _a23 += __shfl_xor_sync(0xffffffffu, _s23, 1);                       \
        float _keep = (sub & 2) ? _a23 : _a01;                               \
        float _send = (sub & 2) ? _a01 : _a23;                               \
        float _s = _keep + __shfl_xor_sync(0xffffffffu, _send, 2);           \
        _s += __shfl_xor_sync(0xffffffffu, _s, 4);                           \
        _s += __shfl_xor_sync(0xffffffffu, _s, 8);                           \
        if (sub < 4) dbuf[sub * 16 + grp] = _s;                              \
        __syncthreads();                                                     \
                                                                             \
        /* s1 = item[n].wa1, replicated per warp (5 shfl) */                 \
        float _p = _it0 * wa1s[lane] + _it1 * wa1s[32 + lane];               \
        _Pragma("unroll")                                                    \
        for (int _o = 16; _o > 0; _o >>= 1)                                  \
            _p += __shfl_xor_sync(0xffffffffu, _p, _o);                      \
                                                                             \
        /* masked leaky-relu softmax, no max-subtraction (|e|<~30 << 88) */  \
        float _e0 = _p + dbuf[lane];                                         \
        float _e1 = _p + dbuf[32 + lane];                                    \
        _e0 = _e0 > 0.f ? _e0 : ALPHA * _e0;                                 \
        _e1 = _e1 > 0.f ? _e1 : ALPHA * _e1;                                 \
        if ((j0) <= 0) _e0 = NEG_INF_V;                                      \
        if ((j1) <= 0) _e1 = NEG_INF_V;                                      \
        const float _x0 = __expf(_e0);                                       \
        const float _x1 = __expf(_e1);                                       \
        float _sm = _x0 + _x1;                                               \
        _Pragma("unroll")                                                    \
        for (int _o = 16; _o > 0; _o >>= 1)                                  \
            _sm += __shfl_xor_sync(0xffffffffu, _sm, _o);                    \
        const float _inv = 1.0f / _sm;                                       \
        const float _att0 = _x0 * _inv;                                      \
        const float _att1 = _x1 * _inv;                                      \
        const float _am0 = __shfl_sync(0xffffffffu, _att0, grp);             \
        const float _am1 = __shfl_sync(0xffffffffu, _att0, 16 + grp);        \
        const float _am2 = __shfl_sync(0xffffffffu, _att1, grp);             \
        const float _am3 = __shfl_sync(0xffffffffu, _att1, 16 + grp);        \
                                                                             \
        /* weighted sum from registers (masked rows: att=0 and v=0) */       \
        float4 _acc;                                                         \
        _acc.x = _am0 * v[0].x; _acc.y = _am0 * v[0].y;                      \
        _acc.z = _am0 * v[0].z; _acc.w = _am0 * v[0].w;                      \
        _acc.x = fmaf(_am1, v[1].x, _acc.x); _acc.y = fmaf(_am1, v[1].y, _acc.y); \
        _acc.z = fmaf(_am1, v[1].z, _acc.z); _acc.w = fmaf(_am1, v[1].w, _acc.w); \
        _acc.x = fmaf(_am2, v[2].x, _acc.x); _acc.y = fmaf(_am2, v[2].y, _acc.y); \
        _acc.z = fmaf(_am2, v[2].z, _acc.z); _acc.w = fmaf(_am2, v[2].w, _acc.w); \
        _acc.x = fmaf(_am3, v[3].x, _acc.x); _acc.y = fmaf(_am3, v[3].y, _acc.y); \
        _acc.z = fmaf(_am3, v[3].z, _acc.z); _acc.w = fmaf(_am3, v[3].w, _acc.w); \
        _acc.x += __shfl_xor_sync(0xffffffffu, _acc.x, 16);                  \
        _acc.y += __shfl_xor_sync(0xffffffffu, _acc.y, 16);                  \
        _acc.z += __shfl_xor_sync(0xffffffffu, _acc.z, 16);                  \
        _acc.w += __shfl_xor_sync(0xffffffffu, _acc.w, 16);                  \
        if (lane < 16)                                                       \
            *reinterpret_cast<float4*>(&part[w * 64 + sub * 4]) = _acc;      \
        __syncthreads();                                                     \
                                                                             \
        if (t < 64) {                                                        \
            float _r = part[t]       + part[64 + t]  + part[128 + t]         \
                     + part[192 + t] + part[256 + t] + part[320 + t]         \
                     + part[384 + t] + part[448 + t]                         \
                     + ((w == 0) ? _it0 : _it1);                             \
            out[_b + t] = _r;                                                \
        }                                                                    \
    }

__global__ __launch_bounds__(256, 4) void gat_kernel(
    const float* __restrict__ item,
    const float* __restrict__ ent,
    const int*   __restrict__ adj,
    const float* __restrict__ W,
    const float* __restrict__ a,
    float*       __restrict__ out)
{
    __shared__ float wa1s[64];
    __shared__ float wa2s[64];
    __shared__ float dbuf[64];
    __shared__ float part[8 * 64];

    const int t    = threadIdx.x;
    const int lane = t & 31;
    const int sub  = t & 15;
    const int grp  = t >> 4;
    const int w    = t >> 5;
    const int S    = gridDim.x;

    // --- Prologue: wa1 = W@a1, wa2 = W@a2 (once per CTA) ---
    {
        const int f = t >> 2, q = t & 3;
        const float* wr = W + f * 64 + q * 16;
        float p1 = 0.f, p2 = 0.f;
#pragma unroll
        for (int i = 0; i < 4; ++i) {
            float4 wv = *reinterpret_cast<const float4*>(wr + i * 4);
            float4 y1 = *reinterpret_cast<const float4*>(a + q * 16 + i * 4);
            float4 y2 = *reinterpret_cast<const float4*>(a + 64 + q * 16 + i * 4);
            p1 += wv.x * y1.x + wv.y * y1.y + wv.z * y1.z + wv.w * y1.w;
            p2 += wv.x * y2.x + wv.y * y2.y + wv.z * y2.z + wv.w * y2.w;
        }
        p1 += __shfl_xor_sync(0xffffffffu, p1, 1);
        p1 += __shfl_xor_sync(0xffffffffu, p1, 2);
        p2 += __shfl_xor_sync(0xffffffffu, p2, 1);
        p2 += __shfl_xor_sync(0xffffffffu, p2, 2);
        if (q == 0) { wa1s[f] = p1; wa2s[f] = p2; }
    }
    __syncthreads();
    const float4 w2 = *reinterpret_cast<const float4*>(&wa2s[sub * 4]);

    // --- 3-stage pipeline: adj 2 ahead, predicated tile 1 ahead, body now ---
    float4 vA[4], vB[4];
    int j0A, j1A, j0B, j1B, j0C, j1C;
    int mk;

    int n = blockIdx.x;
    LOADJ(n, j0A, j1A);
    if (n + S < N_ITEMS) LOADJ(n + S, j0B, j1B);
    MASKOF(j0A, j1A, mk);
    LOADT_P(n, vA, mk);

    while (true) {
        const int nB = n + S;
        const int nC = n + 2 * S;
        // prefetch tile nB (flags jB ready), prefetch flags for nC
        if (nB < N_ITEMS) {
            MASKOF(j0B, j1B, mk);
            LOADT_P(nB, vB, mk);
            if (nC < N_ITEMS) LOADJ(nC, j0C, j1C);
        }
        BODY(n, vA, j0A, j1A);
        if (nB >= N_ITEMS) break;

        const int nD = n + 3 * S;
        // prefetch tile nC (flags jC ready), prefetch flags for nD
        if (nC < N_ITEMS) {
            MASKOF(j0C, j1C, mk);
            LOADT_P(nC, vA, mk);
            if (nD < N_ITEMS) LOADJ(nD, j0A, j1A);
        }
        BODY(nB, vB, j0B, j1B);
        if (nC >= N_ITEMS) break;

        // rotate names: (A := C-tile already in vA) flags: jA holds nD's
        j0B = j0A; j1B = j1A;   // flags for nD -> "next-next" slot
        j0A = j0C; j1A = j1C;   // flags for nC -> current slot
        n = nC;
    }
}

extern "C" void kernel_launch(void* const* d_in, const int* in_sizes, int n_in,
                              void* d_out, int out_size) {
    const float* item = (const float*)d_in[0];
    const float* ent  = (const float*)d_in[1];
    const int*   adj  = (const int*)d_in[2];
    const float* W    = (const float*)d_in[3];
    const float* a    = (const float*)d_in[4];
    float* out = (float*)d_out;

    gat_kernel<<<GRID, 256>>>(item, ent, adj, W, a, out);
}